// round 15
// baseline (speedup 1.0000x reference)
#include <cuda_runtime.h>
#include <cuda_fp16.h>
#include <cstdint>

#define BATCH  1024
#define HIDDEN 4096
#define RDIM   2048

#define BM 128
#define BN 64
#define BK 64
#define THREADS 256
#define NSTG 4
#define AROWB 144                        // 64 fp16 = 128B data + 16B pad
#define APLANE (128 * AROWB)             // 18432 B
#define BPLANE (64 * AROWB)              // 9216 B
#define STG_BYTES (2 * APLANE + 2 * BPLANE)   // 55296
#define STG_OFF 1024
#define OFF_MBAR 768                     // 8 mbarriers x 8B (full[4], empty[4])
#define SMEM_BYTES (STG_OFF + NSTG * STG_BYTES)  // 222208

#define RSCALE 4096.0f
#define RINV   2.44140625e-4f            // 1/4096

// ---- static scratch: pre-split fp16 planes ----
__device__ __half g_Wp[5][2][4194304];   // 5 weights x 2 planes x 2048*2048
__device__ __half g_Xp[2][2097152];      // x_t: 2 planes x 1024*2048
__device__ __half g_Sb[4194304];         // spk_t fp16 (exact): 1024*4096

static __device__ __forceinline__ uint32_t smem_u32(const void* p) {
    uint32_t a;
    asm("{ .reg .u64 t; cvta.to.shared.u64 t, %1; cvt.u32.u64 %0, t; }" : "=r"(a) : "l"(p));
    return a;
}

#define CP16(dst, src) asm volatile("cp.async.cg.shared.global [%0], [%1], 16;" :: "r"(dst), "l"(src))

#define LDSM4(r, addr)                                                          \
    asm volatile("ldmatrix.sync.aligned.m8n8.x4.shared.b16 {%0,%1,%2,%3}, [%4];"\
                 : "=r"((r)[0]), "=r"((r)[1]), "=r"((r)[2]), "=r"((r)[3])       \
                 : "r"(addr))

#define MMAH(c, a, b)                                                           \
    asm volatile("mma.sync.aligned.m16n8k16.row.col.f32.f16.f16.f32 "           \
                 "{%0,%1,%2,%3}, {%4,%5,%6,%7}, {%8,%9}, {%0,%1,%2,%3};"        \
                 : "+f"((c)[0]), "+f"((c)[1]), "+f"((c)[2]), "+f"((c)[3])       \
                 : "r"((a)[0]), "r"((a)[1]), "r"((a)[2]), "r"((a)[3]),          \
                   "r"((b)[0]), "r"((b)[1]))

#define MBARRIER_INIT(a, c) \
    asm volatile("mbarrier.init.shared.b64 [%0], %1;" :: "r"(a), "r"(c) : "memory")
#define MBARRIER_ARRIVE(a) \
    asm volatile("mbarrier.arrive.shared.b64 _, [%0];" :: "r"(a) : "memory")
// .noinc is load-bearing (R13 deadlock without it).
#define CPASYNC_MBAR_ARRIVE(a) \
    asm volatile("cp.async.mbarrier.arrive.noinc.shared.b64 [%0];" :: "r"(a) : "memory")

static __device__ __forceinline__ void mbar_wait(uint32_t mbar, uint32_t parity) {
    uint32_t done;
    asm volatile(
        "{\n\t.reg .pred p;\n\t"
        "mbarrier.try_wait.parity.acquire.cta.shared::cta.b64 p, [%1], %2;\n\t"
        "selp.b32 %0, 1, 0, p;\n\t}"
        : "=r"(done) : "r"(mbar), "r"(parity) : "memory");
    if (!done) {
        asm volatile(
            "{\n\t.reg .pred P1;\n\t"
            "WL_%=:\n\t"
            "mbarrier.try_wait.parity.acquire.cta.shared::cta.b64 P1, [%0], %1, 0x989680;\n\t"
            "@P1 bra.uni WD_%=;\n\t"
            "bra.uni WL_%=;\n\t"
            "WD_%=:\n\t}"
            :: "r"(mbar), "r"(parity) : "memory");
    }
}

static __device__ __forceinline__ void two_sum(float& sum, float& comp, float v) {
    const float s = sum + v;
    const float z = s - sum;
    const float e = (sum - (s - z)) + (v - z);
    sum  = s;
    comp = comp + e;
}

static __device__ __forceinline__ uint32_t pkh(float a, float b) {
    __half2 t = __halves2half2(__float2half_rn(a), __float2half_rn(b));
    return *reinterpret_cast<uint32_t*>(&t);
}

// -------- pre-pass: exact fp16 2-plane split (residual scaled by 4096) --------
__global__ void k_split(const float* __restrict__ w0, const float* __restrict__ w1,
                        const float* __restrict__ w2, const float* __restrict__ w3,
                        const float* __restrict__ w4, const float* __restrict__ x,
                        const float* __restrict__ spk)
{
    const int mat = blockIdx.y;
    const size_t i = ((size_t)blockIdx.x * blockDim.x + threadIdx.x) * 4;

    if (mat == 6) {
        const float4 v = *(const float4*)(spk + i);
        *(uint2*)(g_Sb + i) = make_uint2(pkh(v.x, v.y), pkh(v.z, v.w));  // 0/1 exact
        return;
    }

    const float* src;
    size_t n;
    __half *d0, *d1;
    if (mat < 5) {
        src = (mat == 0) ? w0 : (mat == 1) ? w1 : (mat == 2) ? w2 : (mat == 3) ? w3 : w4;
        n = 4194304; d0 = g_Wp[mat][0]; d1 = g_Wp[mat][1];
    } else {
        src = x; n = 2097152; d0 = g_Xp[0]; d1 = g_Xp[1];
    }
    if (i >= n) return;
    const float4 v = *(const float4*)(src + i);
    float f[4] = {v.x, v.y, v.z, v.w};
    float h0[4], h1[4];
    #pragma unroll
    for (int q = 0; q < 4; ++q) {
        const __half p0 = __float2half_rn(f[q]);
        const float  r  = f[q] - __half2float(p0);    // exact
        h0[q] = __half2float(p0);
        h1[q] = r * RSCALE;                           // scaled residual
    }
    *(uint2*)(d0 + i) = make_uint2(pkh(h0[0], h0[1]), pkh(h0[2], h0[3]));
    *(uint2*)(d1 + i) = make_uint2(pkh(h1[0], h1[1]), pkh(h1[2], h1[3]));
}

// -------- main fused kernel: mbarrier slip pipeline, overlapped LDSM window --------
__global__ __launch_bounds__(THREADS, 1)
void snn_fp16_kernel(const float* __restrict__ mem_t,
                     const float* __restrict__ spk_t,
                     const float* __restrict__ b_t,
                     const float* __restrict__ b_x2in,
                     const float* __restrict__ b_rec4in,
                     const float* __restrict__ b_in2out,
                     const float* __restrict__ b_rec4out,
                     const float* __restrict__ b_out2in,
                     const float* __restrict__ tau_adp,
                     const float* __restrict__ tau_m,
                     float* __restrict__ out)
{
    extern __shared__ char smem[];
    float* smf = (float*)smem;
    const uint32_t sb = smem_u32(smem);

    const int tid  = threadIdx.x;
    const int wid  = tid >> 5;
    const int lane = tid & 31;
    const int t = lane & 3;
    const int g = lane >> 2;
    const int wm = (wid & 3) * 32;      // 4 warps down M (128)
    const int wn = (wid >> 2) * 32;     // 2 warps across N (64)

    const int n_tile = blockIdx.x * BN;
    const int m_tile = blockIdx.y * BM;
    const bool outh  = (n_tile < RDIM);
    const int jbase  = outh ? n_tile : (n_tile - RDIM);

    if (tid == 0) {
        #pragma unroll
        for (int b = 0; b < NSTG; ++b) {
            MBARRIER_INIT(sb + OFF_MBAR + b * 8, THREADS);              // full[b]
            MBARRIER_INIT(sb + OFF_MBAR + (NSTG + b) * 8, THREADS);     // empty[b]
        }
    }
    if (tid < 64) {
        const int n = n_tile + tid;
        float bias;
        if (outh) bias = b_rec4out[n] + b_in2out[n];
        else { const int jn = n - RDIM; bias = b_x2in[jn] + b_rec4in[jn] + b_out2in[jn]; }
        smf[tid]       = bias;
        smf[64 + tid]  = 1.0f / (1.0f + __expf(-tau_m[n]));
        smf[128 + tid] = 1.0f / (1.0f + __expf(-tau_adp[n]));
    }
    __syncthreads();   // only CTA-wide sync in the kernel

    const uint32_t FULLB  = sb + OFF_MBAR;
    const uint32_t EMPTYB = sb + OFF_MBAR + NSTG * 8;

    const uint32_t aoff = (uint32_t)(wm + (lane & 15)) * AROWB + (uint32_t)(lane >> 4) * 16;
    const uint32_t boff = (uint32_t)(wn + ((lane >> 4) << 3) + (lane & 7)) * AROWB
                        + (uint32_t)((lane >> 3) & 1) * 16;

    const int S = outh ? 64 : 96;       // 32 stages of BK=64 per source

    auto issue = [&](int s) {
        const int src = s >> 5;
        const int k0  = (s & 31) * BK;
        const int buf = s & (NSTG - 1);
        const uint32_t stga = sb + STG_OFF + buf * STG_BYTES;

        const __half* Wb;
        const __half* Ab = nullptr;
        bool xsrc = false;
        if (outh) {
            if (src == 0) { Ab = g_Sb;        Wb = g_Wp[0][0]; }
            else          { Ab = g_Sb + 2048; Wb = g_Wp[1][0]; }
        } else {
            if (src == 0)      { xsrc = true;      Wb = g_Wp[2][0]; }
            else if (src == 1) { Ab = g_Sb + 2048; Wb = g_Wp[3][0]; }
            else               { Ab = g_Sb;        Wb = g_Wp[4][0]; }
        }

        #pragma unroll
        for (int i = 0; i < 4; ++i) {
            const int id = tid + i * 256;
            const int p = id >> 9, rem = id & 511, row = rem >> 3, c = rem & 7;
            const __half* gsrc = Wb + (size_t)p * 4194304
                                    + (size_t)(jbase + row) * 2048 + k0 + c * 8;
            CP16(stga + 2 * APLANE + p * BPLANE + row * AROWB + c * 16, gsrc);
        }
        if (xsrc) {
            #pragma unroll
            for (int i = 0; i < 8; ++i) {
                const int id = tid + i * 256;
                const int p = id >> 10, rem = id & 1023, row = rem >> 3, c = rem & 7;
                const __half* gsrc = (&g_Xp[0][0]) + (size_t)p * 2097152
                                     + (size_t)(m_tile + row) * 2048 + k0 + c * 8;
                CP16(stga + p * APLANE + row * AROWB + c * 16, gsrc);
            }
        } else {
            #pragma unroll
            for (int i = 0; i < 4; ++i) {
                const int id = tid + i * 256;
                const int row = id >> 3, c = id & 7;
                const __half* gsrc = Ab + (size_t)(m_tile + row) * 4096 + k0 + c * 8;
                CP16(stga + row * AROWB + c * 16, gsrc);
            }
        }
        CPASYNC_MBAR_ARRIVE(FULLB + buf * 8);
    };

    float sum[2][4][4], comp[2][4][4], tmp[2][4][4], corr[2][4][4];
    #pragma unroll
    for (int mi = 0; mi < 2; ++mi)
        #pragma unroll
        for (int ni = 0; ni < 4; ++ni)
            #pragma unroll
            for (int r = 0; r < 4; ++r) {
                sum[mi][ni][r] = 0.0f; comp[mi][ni][r] = 0.0f;
                tmp[mi][ni][r] = 0.0f; corr[mi][ni][r] = 0.0f;
            }

    #pragma unroll
    for (int p = 0; p < 3; ++p) {
        mbar_wait(EMPTYB + (p & (NSTG - 1)) * 8, (((p >> 2) & 1) ^ 1));
        issue(p);
    }

    for (int s = 0; s < S; ++s) {
        const int p = s + 3;
        if (p < S) {
            mbar_wait(EMPTYB + (p & (NSTG - 1)) * 8, (((p >> 2) & 1) ^ 1));
            issue(p);
        }
        mbar_wait(FULLB + (s & (NSTG - 1)) * 8, ((s >> 2) & 1));

        const int buf = s & (NSTG - 1);
        const bool is_x = (!outh) && (s < 32);
        const uint32_t stga = sb + STG_OFF + buf * STG_BYTES;
        const uint32_t Ab   = stga + aoff;
        const uint32_t Bb   = stga + 2 * APLANE + boff;

        #pragma unroll
        for (int kk = 0; kk < 4; ++kk) {
            const uint32_t kb = kk * 32;

            // ---- issue ALL fragment loads for this k-step up front ----
            uint32_t a0[2][4], a1[2][4];
            uint32_t bfr0[8], bfr1[8];     // separate regs per plane: no WAR serialization
            #pragma unroll
            for (int mi = 0; mi < 2; ++mi)
                LDSM4(a0[mi], Ab + mi * (16 * AROWB) + kb);
            LDSM4(bfr0,     Bb + kb);
            LDSM4(bfr0 + 4, Bb + 16 * AROWB + kb);
            LDSM4(bfr1,     Bb + BPLANE + kb);
            LDSM4(bfr1 + 4, Bb + BPLANE + 16 * AROWB + kb);
            if (is_x) {
                #pragma unroll
                for (int mi = 0; mi < 2; ++mi)
                    LDSM4(a1[mi], Ab + APLANE + mi * (16 * AROWB) + kb);
            }

            // ---- MMA bursts (loads for later planes already in flight) ----
            #pragma unroll
            for (int ni = 0; ni < 4; ++ni)
                #pragma unroll
                for (int mi = 0; mi < 2; ++mi)
                    MMAH(tmp[mi][ni], a0[mi], (bfr0 + ni * 2));
            #pragma unroll
            for (int ni = 0; ni < 4; ++ni)
                #pragma unroll
                for (int mi = 0; mi < 2; ++mi)
                    MMAH(corr[mi][ni], a0[mi], (bfr1 + ni * 2));
            if (is_x) {
                #pragma unroll
                for (int ni = 0; ni < 4; ++ni)
                    #pragma unroll
                    for (int mi = 0; mi < 2; ++mi)
                        MMAH(corr[mi][ni], a1[mi], (bfr0 + ni * 2));
            }
        }

        MBARRIER_ARRIVE(EMPTYB + buf * 8);

        // compensated flush every 2 stages (128 k per group)
        if (s & 1) {
            #pragma unroll
            for (int mi = 0; mi < 2; ++mi)
                #pragma unroll
                for (int ni = 0; ni < 4; ++ni)
                    #pragma unroll
                    for (int r = 0; r < 4; ++r) {
                        two_sum(sum[mi][ni][r], comp[mi][ni][r], tmp[mi][ni][r]);
                        tmp[mi][ni][r] = 0.0f;
                    }
        }
    }

    // ---------------- fused epilogue ----------------
    const size_t plane = (size_t)BATCH * HIDDEN;
    #pragma unroll
    for (int mi = 0; mi < 2; ++mi) {
        #pragma unroll
        for (int ni = 0; ni < 4; ++ni) {
            const int lc = wn + ni * 8 + t * 2;
            const float bi0 = smf[lc],       bi1 = smf[lc + 1];
            const float tm0 = smf[64 + lc],  tm1 = smf[64 + lc + 1];
            const float ta0 = smf[128 + lc], ta1 = smf[128 + lc + 1];
            #pragma unroll
            for (int hh = 0; hh < 2; ++hh) {
                const int row = m_tile + wm + mi * 16 + g + hh * 8;
                const size_t idx = (size_t)row * HIDDEN + n_tile + lc;
                const float2 sp = *(const float2*)(spk_t + idx);
                const float2 bt = *(const float2*)(b_t   + idx);
                const float2 mt = *(const float2*)(mem_t + idx);

                const int r0 = hh * 2 + 0, r1 = hh * 2 + 1;
                const float i0 = (sum[mi][ni][r0] + (comp[mi][ni][r0] + corr[mi][ni][r0] * RINV)) + bi0;
                const float i1 = (sum[mi][ni][r1] + (comp[mi][ni][r1] + corr[mi][ni][r1] * RINV)) + bi1;

                const float bb0 = ta0 * bt.x + (1.0f - ta0) * sp.x;
                const float bb1 = ta1 * bt.y + (1.0f - ta1) * sp.y;
                const float th0 = 0.1f + 1.8f * bb0;
                const float th1 = 0.1f + 1.8f * bb1;
                const float me0 = mt.x * tm0 + (1.0f - tm0) * 3.0f * i0 - th0 * sp.x;
                const float me1 = mt.y * tm1 + (1.0f - tm1) * 3.0f * i1 - th1 * sp.y;
                const float s0 = (me0 - th0) > 0.0f ? 1.0f : 0.0f;
                const float s1 = (me1 - th1) > 0.0f ? 1.0f : 0.0f;

                float2 vm; vm.x = me0; vm.y = me1;
                float2 vs; vs.x = s0;  vs.y = s1;
                float2 vb; vb.x = bb0; vb.y = bb1;
                *(float2*)(out + idx)             = vm;
                *(float2*)(out + plane + idx)     = vs;
                *(float2*)(out + 2 * plane + idx) = vb;
            }
        }
    }
}

extern "C" void kernel_launch(void* const* d_in, const int* in_sizes, int n_in,
                              void* d_out, int out_size)
{
    const float* x_t       = (const float*)d_in[0];
    const float* mem_t     = (const float*)d_in[1];
    const float* spk_t     = (const float*)d_in[2];
    const float* b_t       = (const float*)d_in[3];
    const float* W_x2in    = (const float*)d_in[4];
    const float* b_x2in    = (const float*)d_in[5];
    const float* W_rec4in  = (const float*)d_in[6];
    const float* b_rec4in  = (const float*)d_in[7];
    const float* W_in2out  = (const float*)d_in[8];
    const float* b_in2out  = (const float*)d_in[9];
    const float* W_rec4out = (const float*)d_in[10];
    const float* b_rec4out = (const float*)d_in[11];
    const float* W_out2in  = (const float*)d_in[12];
    const float* b_out2in  = (const float*)d_in[13];
    const float* tau_adp   = (const float*)d_in[14];
    const float* tau_m     = (const float*)d_in[15];
    float* out = (float*)d_out;

    // pre-pass (y: 0=rec4out, 1=in2out, 2=x2in, 3=rec4in, 4=out2in, 5=x_t, 6=spk)
    dim3 sgrid(4096, 7);
    k_split<<<sgrid, 256>>>(W_rec4out, W_in2out, W_x2in, W_rec4in, W_out2in, x_t, spk_t);

    cudaFuncSetAttribute(snn_fp16_kernel, cudaFuncAttributeMaxDynamicSharedMemorySize, SMEM_BYTES);
    dim3 grid(HIDDEN / BN, BATCH / BM);   // (64, 8) = 512 CTAs
    snn_fp16_kernel<<<grid, THREADS, SMEM_BYTES>>>(mem_t, spk_t, b_t,
                                                   b_x2in, b_rec4in, b_in2out,
                                                   b_rec4out, b_out2in,
                                                   tau_adp, tau_m, out);
}

// round 16
// speedup vs baseline: 1.5500x; 1.5500x over previous
#include <cuda_runtime.h>
#include <cuda_fp16.h>
#include <cstdint>

#define BATCH  1024
#define HIDDEN 4096
#define RDIM   2048

#define BM 128
#define BN 64
#define BK 64
#define THREADS 256
#define NSTG 4
#define AROWB 144                        // 64 fp16 = 128B data + 16B pad
#define APLANE (128 * AROWB)             // 18432 B
#define BPLANE (64 * AROWB)              // 9216 B
#define STG_BYTES (2 * APLANE + 2 * BPLANE)   // 55296
#define STG_OFF 1024
#define OFF_MBAR 768                     // 8 mbarriers x 8B (full[4], empty[4])
#define SMEM_BYTES (STG_OFF + NSTG * STG_BYTES)  // 222208

#define RSCALE 4096.0f
#define RINV   2.44140625e-4f            // 1/4096

// ---- static scratch: pre-split fp16 planes ----
__device__ __half g_Wp[5][2][4194304];   // 5 weights x 2 planes x 2048*2048
__device__ __half g_Xp[2][2097152];      // x_t: 2 planes x 1024*2048
__device__ __half g_Sb[4194304];         // spk_t fp16 (exact): 1024*4096

static __device__ __forceinline__ uint32_t smem_u32(const void* p) {
    uint32_t a;
    asm("{ .reg .u64 t; cvta.to.shared.u64 t, %1; cvt.u32.u64 %0, t; }" : "=r"(a) : "l"(p));
    return a;
}

#define CP16(dst, src) asm volatile("cp.async.cg.shared.global [%0], [%1], 16;" :: "r"(dst), "l"(src))

#define LDSM4(r, addr)                                                          \
    asm volatile("ldmatrix.sync.aligned.m8n8.x4.shared.b16 {%0,%1,%2,%3}, [%4];"\
                 : "=r"((r)[0]), "=r"((r)[1]), "=r"((r)[2]), "=r"((r)[3])       \
                 : "r"(addr))

#define MMAH(c, a, b)                                                           \
    asm volatile("mma.sync.aligned.m16n8k16.row.col.f32.f16.f16.f32 "           \
                 "{%0,%1,%2,%3}, {%4,%5,%6,%7}, {%8,%9}, {%0,%1,%2,%3};"        \
                 : "+f"((c)[0]), "+f"((c)[1]), "+f"((c)[2]), "+f"((c)[3])       \
                 : "r"((a)[0]), "r"((a)[1]), "r"((a)[2]), "r"((a)[3]),          \
                   "r"((b)[0]), "r"((b)[1]))

#define MBARRIER_INIT(a, c) \
    asm volatile("mbarrier.init.shared.b64 [%0], %1;" :: "r"(a), "r"(c) : "memory")
#define MBARRIER_ARRIVE(a) \
    asm volatile("mbarrier.arrive.shared.b64 _, [%0];" :: "r"(a) : "memory")
// .noinc is load-bearing (R13 deadlock without it).
#define CPASYNC_MBAR_ARRIVE(a) \
    asm volatile("cp.async.mbarrier.arrive.noinc.shared.b64 [%0];" :: "r"(a) : "memory")

static __device__ __forceinline__ void mbar_wait(uint32_t mbar, uint32_t parity) {
    uint32_t done;
    asm volatile(
        "{\n\t.reg .pred p;\n\t"
        "mbarrier.try_wait.parity.acquire.cta.shared::cta.b64 p, [%1], %2;\n\t"
        "selp.b32 %0, 1, 0, p;\n\t}"
        : "=r"(done) : "r"(mbar), "r"(parity) : "memory");
    if (!done) {
        asm volatile(
            "{\n\t.reg .pred P1;\n\t"
            "WL_%=:\n\t"
            "mbarrier.try_wait.parity.acquire.cta.shared::cta.b64 P1, [%0], %1, 0x989680;\n\t"
            "@P1 bra.uni WD_%=;\n\t"
            "bra.uni WL_%=;\n\t"
            "WD_%=:\n\t}"
            :: "r"(mbar), "r"(parity) : "memory");
    }
}

static __device__ __forceinline__ void two_sum(float& sum, float& comp, float v) {
    const float s = sum + v;
    const float z = s - sum;
    const float e = (sum - (s - z)) + (v - z);
    sum  = s;
    comp = comp + e;
}

static __device__ __forceinline__ uint32_t pkh(float a, float b) {
    __half2 t = __halves2half2(__float2half_rn(a), __float2half_rn(b));
    return *reinterpret_cast<uint32_t*>(&t);
}

// -------- pre-pass: exact fp16 2-plane split (residual scaled by 4096) --------
__global__ void k_split(const float* __restrict__ w0, const float* __restrict__ w1,
                        const float* __restrict__ w2, const float* __restrict__ w3,
                        const float* __restrict__ w4, const float* __restrict__ x,
                        const float* __restrict__ spk)
{
    const int mat = blockIdx.y;
    const size_t i = ((size_t)blockIdx.x * blockDim.x + threadIdx.x) * 4;

    if (mat == 6) {
        const float4 v = *(const float4*)(spk + i);
        *(uint2*)(g_Sb + i) = make_uint2(pkh(v.x, v.y), pkh(v.z, v.w));  // 0/1 exact
        return;
    }

    const float* src;
    size_t n;
    __half *d0, *d1;
    if (mat < 5) {
        src = (mat == 0) ? w0 : (mat == 1) ? w1 : (mat == 2) ? w2 : (mat == 3) ? w3 : w4;
        n = 4194304; d0 = g_Wp[mat][0]; d1 = g_Wp[mat][1];
    } else {
        src = x; n = 2097152; d0 = g_Xp[0]; d1 = g_Xp[1];
    }
    if (i >= n) return;
    const float4 v = *(const float4*)(src + i);
    float f[4] = {v.x, v.y, v.z, v.w};
    float h0[4], h1[4];
    #pragma unroll
    for (int q = 0; q < 4; ++q) {
        const __half p0 = __float2half_rn(f[q]);
        const float  r  = f[q] - __half2float(p0);    // exact
        h0[q] = __half2float(p0);
        h1[q] = r * RSCALE;                           // scaled residual
    }
    *(uint2*)(d0 + i) = make_uint2(pkh(h0[0], h0[1]), pkh(h0[2], h0[3]));
    *(uint2*)(d1 + i) = make_uint2(pkh(h1[0], h1[1]), pkh(h1[2], h1[3]));
}

// -------- main fused kernel: mbarrier slip pipeline (R14 structure) --------
__global__ __launch_bounds__(THREADS, 1)
void snn_fp16_kernel(const float* __restrict__ mem_t,
                     const float* __restrict__ spk_t,
                     const float* __restrict__ b_t,
                     const float* __restrict__ b_x2in,
                     const float* __restrict__ b_rec4in,
                     const float* __restrict__ b_in2out,
                     const float* __restrict__ b_rec4out,
                     const float* __restrict__ b_out2in,
                     const float* __restrict__ tau_adp,
                     const float* __restrict__ tau_m,
                     float* __restrict__ out)
{
    extern __shared__ char smem[];
    float* smf = (float*)smem;
    const uint32_t sb = smem_u32(smem);

    const int tid  = threadIdx.x;
    const int wid  = tid >> 5;
    const int lane = tid & 31;
    const int t = lane & 3;
    const int g = lane >> 2;
    const int wm = (wid & 3) * 32;      // 4 warps down M (128)
    const int wn = (wid >> 2) * 32;     // 2 warps across N (64)

    const int n_tile = blockIdx.x * BN;
    const int m_tile = blockIdx.y * BM;
    const bool outh  = (n_tile < RDIM);
    const int jbase  = outh ? n_tile : (n_tile - RDIM);

    if (tid == 0) {
        #pragma unroll
        for (int b = 0; b < NSTG; ++b) {
            MBARRIER_INIT(sb + OFF_MBAR + b * 8, THREADS);              // full[b]
            MBARRIER_INIT(sb + OFF_MBAR + (NSTG + b) * 8, THREADS);     // empty[b]
        }
    }
    if (tid < 64) {
        const int n = n_tile + tid;
        float bias;
        if (outh) bias = b_rec4out[n] + b_in2out[n];
        else { const int jn = n - RDIM; bias = b_x2in[jn] + b_rec4in[jn] + b_out2in[jn]; }
        smf[tid]       = bias;
        smf[64 + tid]  = 1.0f / (1.0f + __expf(-tau_m[n]));
        smf[128 + tid] = 1.0f / (1.0f + __expf(-tau_adp[n]));
    }
    __syncthreads();   // only CTA-wide sync in the kernel

    const uint32_t FULLB  = sb + OFF_MBAR;
    const uint32_t EMPTYB = sb + OFF_MBAR + NSTG * 8;

    const uint32_t aoff = (uint32_t)(wm + (lane & 15)) * AROWB + (uint32_t)(lane >> 4) * 16;
    const uint32_t boff = (uint32_t)(wn + ((lane >> 4) << 3) + (lane & 7)) * AROWB
                        + (uint32_t)((lane >> 3) & 1) * 16;

    const int S = outh ? 64 : 96;       // 32 stages of BK=64 per source

    auto issue = [&](int s) {
        const int src = s >> 5;
        const int k0  = (s & 31) * BK;
        const int buf = s & (NSTG - 1);
        const uint32_t stga = sb + STG_OFF + buf * STG_BYTES;

        const __half* Wb;
        const __half* Ab = nullptr;
        bool xsrc = false;
        if (outh) {
            if (src == 0) { Ab = g_Sb;        Wb = g_Wp[0][0]; }
            else          { Ab = g_Sb + 2048; Wb = g_Wp[1][0]; }
        } else {
            if (src == 0)      { xsrc = true;      Wb = g_Wp[2][0]; }
            else if (src == 1) { Ab = g_Sb + 2048; Wb = g_Wp[3][0]; }
            else               { Ab = g_Sb;        Wb = g_Wp[4][0]; }
        }

        #pragma unroll
        for (int i = 0; i < 4; ++i) {
            const int id = tid + i * 256;
            const int p = id >> 9, rem = id & 511, row = rem >> 3, c = rem & 7;
            const __half* gsrc = Wb + (size_t)p * 4194304
                                    + (size_t)(jbase + row) * 2048 + k0 + c * 8;
            CP16(stga + 2 * APLANE + p * BPLANE + row * AROWB + c * 16, gsrc);
        }
        if (xsrc) {
            #pragma unroll
            for (int i = 0; i < 8; ++i) {
                const int id = tid + i * 256;
                const int p = id >> 10, rem = id & 1023, row = rem >> 3, c = rem & 7;
                const __half* gsrc = (&g_Xp[0][0]) + (size_t)p * 2097152
                                     + (size_t)(m_tile + row) * 2048 + k0 + c * 8;
                CP16(stga + p * APLANE + row * AROWB + c * 16, gsrc);
            }
        } else {
            #pragma unroll
            for (int i = 0; i < 4; ++i) {
                const int id = tid + i * 256;
                const int row = id >> 3, c = id & 7;
                const __half* gsrc = Ab + (size_t)(m_tile + row) * 4096 + k0 + c * 8;
                CP16(stga + row * AROWB + c * 16, gsrc);
            }
        }
        CPASYNC_MBAR_ARRIVE(FULLB + buf * 8);
    };

    float sum[2][4][4], comp[2][4][4], tmp[2][4][4], corr[2][4][4];
    #pragma unroll
    for (int mi = 0; mi < 2; ++mi)
        #pragma unroll
        for (int ni = 0; ni < 4; ++ni)
            #pragma unroll
            for (int r = 0; r < 4; ++r) {
                sum[mi][ni][r] = 0.0f; comp[mi][ni][r] = 0.0f;
                tmp[mi][ni][r] = 0.0f; corr[mi][ni][r] = 0.0f;
            }

    #pragma unroll
    for (int p = 0; p < 3; ++p) {
        mbar_wait(EMPTYB + (p & (NSTG - 1)) * 8, (((p >> 2) & 1) ^ 1));
        issue(p);
    }

    for (int s = 0; s < S; ++s) {
        const int p = s + 3;
        if (p < S) {
            mbar_wait(EMPTYB + (p & (NSTG - 1)) * 8, (((p >> 2) & 1) ^ 1));
            issue(p);
        }
        mbar_wait(FULLB + (s & (NSTG - 1)) * 8, ((s >> 2) & 1));

        const int buf = s & (NSTG - 1);
        const bool is_x = (!outh) && (s < 32);
        const uint32_t stga = sb + STG_OFF + buf * STG_BYTES;
        const uint32_t Ab   = stga + aoff;
        const uint32_t Bb   = stga + 2 * APLANE + boff;

        #pragma unroll
        for (int kk = 0; kk < 4; ++kk) {
            const uint32_t kb = kk * 32;

            uint32_t a0[2][4], a1[2][4];
            #pragma unroll
            for (int mi = 0; mi < 2; ++mi)
                LDSM4(a0[mi], Ab + mi * (16 * AROWB) + kb);
            if (is_x) {
                #pragma unroll
                for (int mi = 0; mi < 2; ++mi)
                    LDSM4(a1[mi], Ab + APLANE + mi * (16 * AROWB) + kb);
            }

            uint32_t bfr[8];

            // ---- plane 0: main + (x) a1*b0 ----
            LDSM4(bfr,     Bb + kb);
            LDSM4(bfr + 4, Bb + 16 * AROWB + kb);
            #pragma unroll
            for (int ni = 0; ni < 4; ++ni)
                #pragma unroll
                for (int mi = 0; mi < 2; ++mi)
                    MMAH(tmp[mi][ni], a0[mi], (bfr + ni * 2));
            if (is_x) {
                #pragma unroll
                for (int ni = 0; ni < 4; ++ni)
                    #pragma unroll
                    for (int mi = 0; mi < 2; ++mi)
                        MMAH(corr[mi][ni], a1[mi], (bfr + ni * 2));
            }

            // ---- plane 1: a0*b1 (scaled residual) ----
            LDSM4(bfr,     Bb + BPLANE + kb);
            LDSM4(bfr + 4, Bb + BPLANE + 16 * AROWB + kb);

            // last smem read of this buffer happens in kk==3 -> release early
            if (kk == 3) MBARRIER_ARRIVE(EMPTYB + buf * 8);

            #pragma unroll
            for (int ni = 0; ni < 4; ++ni)
                #pragma unroll
                for (int mi = 0; mi < 2; ++mi)
                    MMAH(corr[mi][ni], a0[mi], (bfr + ni * 2));
        }

        // compensated flush every 2 stages (128 k per group)
        if (s & 1) {
            #pragma unroll
            for (int mi = 0; mi < 2; ++mi)
                #pragma unroll
                for (int ni = 0; ni < 4; ++ni)
                    #pragma unroll
                    for (int r = 0; r < 4; ++r) {
                        two_sum(sum[mi][ni][r], comp[mi][ni][r], tmp[mi][ni][r]);
                        tmp[mi][ni][r] = 0.0f;
                    }
        }
    }

    // ---------------- fused epilogue ----------------
    const size_t plane = (size_t)BATCH * HIDDEN;
    #pragma unroll
    for (int mi = 0; mi < 2; ++mi) {
        #pragma unroll
        for (int ni = 0; ni < 4; ++ni) {
            const int lc = wn + ni * 8 + t * 2;
            const float bi0 = smf[lc],       bi1 = smf[lc + 1];
            const float tm0 = smf[64 + lc],  tm1 = smf[64 + lc + 1];
            const float ta0 = smf[128 + lc], ta1 = smf[128 + lc + 1];
            #pragma unroll
            for (int hh = 0; hh < 2; ++hh) {
                const int row = m_tile + wm + mi * 16 + g + hh * 8;
                const size_t idx = (size_t)row * HIDDEN + n_tile + lc;
                const float2 sp = *(const float2*)(spk_t + idx);
                const float2 bt = *(const float2*)(b_t   + idx);
                const float2 mt = *(const float2*)(mem_t + idx);

                const int r0 = hh * 2 + 0, r1 = hh * 2 + 1;
                const float i0 = (sum[mi][ni][r0] + (comp[mi][ni][r0] + corr[mi][ni][r0] * RINV)) + bi0;
                const float i1 = (sum[mi][ni][r1] + (comp[mi][ni][r1] + corr[mi][ni][r1] * RINV)) + bi1;

                const float bb0 = ta0 * bt.x + (1.0f - ta0) * sp.x;
                const float bb1 = ta1 * bt.y + (1.0f - ta1) * sp.y;
                const float th0 = 0.1f + 1.8f * bb0;
                const float th1 = 0.1f + 1.8f * bb1;
                const float me0 = mt.x * tm0 + (1.0f - tm0) * 3.0f * i0 - th0 * sp.x;
                const float me1 = mt.y * tm1 + (1.0f - tm1) * 3.0f * i1 - th1 * sp.y;
                const float s0 = (me0 - th0) > 0.0f ? 1.0f : 0.0f;
                const float s1 = (me1 - th1) > 0.0f ? 1.0f : 0.0f;

                float2 vm; vm.x = me0; vm.y = me1;
                float2 vs; vs.x = s0;  vs.y = s1;
                float2 vb; vb.x = bb0; vb.y = bb1;
                *(float2*)(out + idx)             = vm;
                *(float2*)(out + plane + idx)     = vs;
                *(float2*)(out + 2 * plane + idx) = vb;
            }
        }
    }
}

extern "C" void kernel_launch(void* const* d_in, const int* in_sizes, int n_in,
                              void* d_out, int out_size)
{
    const float* x_t       = (const float*)d_in[0];
    const float* mem_t     = (const float*)d_in[1];
    const float* spk_t     = (const float*)d_in[2];
    const float* b_t       = (const float*)d_in[3];
    const float* W_x2in    = (const float*)d_in[4];
    const float* b_x2in    = (const float*)d_in[5];
    const float* W_rec4in  = (const float*)d_in[6];
    const float* b_rec4in  = (const float*)d_in[7];
    const float* W_in2out  = (const float*)d_in[8];
    const float* b_in2out  = (const float*)d_in[9];
    const float* W_rec4out = (const float*)d_in[10];
    const float* b_rec4out = (const float*)d_in[11];
    const float* W_out2in  = (const float*)d_in[12];
    const float* b_out2in  = (const float*)d_in[13];
    const float* tau_adp   = (const float*)d_in[14];
    const float* tau_m     = (const float*)d_in[15];
    float* out = (float*)d_out;

    // pre-pass (y: 0=rec4out, 1=in2out, 2=x2in, 3=rec4in, 4=out2in, 5=x_t, 6=spk)
    dim3 sgrid(4096, 7);
    k_split<<<sgrid, 256>>>(W_rec4out, W_in2out, W_x2in, W_rec4in, W_out2in, x_t, spk_t);

    cudaFuncSetAttribute(snn_fp16_kernel, cudaFuncAttributeMaxDynamicSharedMemorySize, SMEM_BYTES);
    dim3 grid(HIDDEN / BN, BATCH / BM);   // (64, 8) = 512 CTAs
    snn_fp16_kernel<<<grid, THREADS, SMEM_BYTES>>>(mem_t, spk_t, b_t,
                                                   b_x2in, b_rec4in, b_in2out,
                                                   b_rec4out, b_out2in,
                                                   tau_adp, tau_m, out);
}